// round 11
// baseline (speedup 1.0000x reference)
#include <cuda_runtime.h>
#include <cuda_bf16.h>
#include <stdint.h>
#include <math.h>

// ---------------------------------------------------------------------------
// Problem constants
// ---------------------------------------------------------------------------
#define RR 128
#define CC 256
#define EE 768
#define HH 12
#define DD 64
#define MTOK (RR * CC)            // 32768 tokens
#define QSCALE (0.0110485434560398f)   // (1/8) / sqrt(128)
#define RSPLIT 8
#define RCHUNK (RR / RSPLIT)      // 16

// ---------------------------------------------------------------------------
// mma.sync GEMM tiling: CTA 128x128, BK=32, 8 warps (4M x 2N)
// ---------------------------------------------------------------------------
#define BM 128
#define BN 128
#define BK 32
#define NKB (EE / BK)             // 24
#define KPAD 40                   // bf16 per smem row (32 + 8 pad) = 80 B
#define ROWB (KPAD * 2)           // 80 bytes
#define TILE_B (BM * ROWB)        // 10240 bytes per plane tile
#define AHI 0
#define ALO TILE_B
#define BHI (2 * TILE_B)
#define BLO (3 * TILE_B)
#define BUF_B (4 * TILE_B)        // 40960
#define SMEM_TOTAL (2 * BUF_B)    // 81920

// context kernel smem
#define VROWB 144                 // 64 bf16 = 128 B + 16 pad
#define CPTILE (128 * ROWB)       // 10240
#define CVTILE (32 * VROWB)       // 4608
#define CPHI 0
#define CPLO CPTILE
#define CVHI (2 * CPTILE)
#define CVLO (2 * CPTILE + CVTILE)
#define CBUF_B (2 * CPTILE + 2 * CVTILE)   // 29696
#define CSMEM_TOTAL (2 * CBUF_B)           // 59392

// ---------------------------------------------------------------------------
// Device global scratch: separate hi / lo bf16 planes
// ---------------------------------------------------------------------------
__device__ __nv_bfloat16 g_xh[(size_t)MTOK * EE], g_xl[(size_t)MTOK * EE];
__device__ __nv_bfloat16 g_wth[4 * (size_t)EE * EE], g_wtl[4 * (size_t)EE * EE];
__device__ __nv_bfloat16 g_qh[(size_t)MTOK * EE],  g_ql[(size_t)MTOK * EE];
__device__ __nv_bfloat16 g_kh[(size_t)MTOK * EE],  g_kl[(size_t)MTOK * EE];
__device__ __nv_bfloat16 g_vh[(size_t)MTOK * EE],  g_vl[(size_t)MTOK * EE];
__device__ __nv_bfloat16 g_ch[(size_t)MTOK * EE],  g_cl[(size_t)MTOK * EE];
__device__ __nv_bfloat16 g_ph[(size_t)HH * CC * CC], g_pl[(size_t)HH * CC * CC];
__device__ float         g_lpart[(size_t)RSPLIT * HH * CC * CC];

// ---------------------------------------------------------------------------
// Helpers
// ---------------------------------------------------------------------------
__device__ __forceinline__ uint32_t smem_to_u32(const void* p) {
    uint32_t a;
    asm("{ .reg .u64 t; cvta.to.shared.u64 t, %1; cvt.u32.u64 %0, t; }"
        : "=r"(a) : "l"(p));
    return a;
}

#define CP16(saddr, gptr) \
    asm volatile("cp.async.cg.shared.global [%0], [%1], 16;" \
        :: "r"(saddr), "l"(gptr) : "memory")
#define CPCOMMIT() asm volatile("cp.async.commit_group;" ::: "memory")
#define CPWAIT0()  asm volatile("cp.async.wait_group 0;" ::: "memory")

#define LDSM4(r, addr) \
    asm volatile("ldmatrix.sync.aligned.m8n8.x4.shared.b16 {%0,%1,%2,%3}, [%4];" \
        : "=r"((r)[0]), "=r"((r)[1]), "=r"((r)[2]), "=r"((r)[3]) : "r"(addr))

#define LDSM4T(r, addr) \
    asm volatile("ldmatrix.sync.aligned.m8n8.x4.trans.shared.b16 {%0,%1,%2,%3}, [%4];" \
        : "=r"((r)[0]), "=r"((r)[1]), "=r"((r)[2]), "=r"((r)[3]) : "r"(addr))

__device__ __forceinline__ void mma_bf16(float* c, const uint32_t* a,
                                         uint32_t b0, uint32_t b1) {
    asm volatile(
        "mma.sync.aligned.m16n8k16.row.col.f32.bf16.bf16.f32 "
        "{%0,%1,%2,%3}, {%4,%5,%6,%7}, {%8,%9}, {%0,%1,%2,%3};"
        : "+f"(c[0]), "+f"(c[1]), "+f"(c[2]), "+f"(c[3])
        : "r"(a[0]), "r"(a[1]), "r"(a[2]), "r"(a[3]), "r"(b0), "r"(b1));
}

__device__ __forceinline__ void split_bf16(float f, __nv_bfloat16& h, __nv_bfloat16& l) {
    h = __float2bfloat16(f);
    l = __float2bfloat16(f - __bfloat162float(h));
}

// store a pair (v0,v1) into hi & lo planes at elem index idx (idx even)
__device__ __forceinline__ void store_split2(
    __nv_bfloat16* Ph, __nv_bfloat16* Pl, size_t idx, float v0, float v1)
{
    __nv_bfloat16 h0, l0, h1, l1;
    split_bf16(v0, h0, l0);
    split_bf16(v1, h1, l1);
    uint32_t uh = (uint32_t)__bfloat16_as_ushort(h0) | ((uint32_t)__bfloat16_as_ushort(h1) << 16);
    uint32_t ul = (uint32_t)__bfloat16_as_ushort(l0) | ((uint32_t)__bfloat16_as_ushort(l1) << 16);
    *(uint32_t*)(Ph + idx) = uh;
    *(uint32_t*)(Pl + idx) = ul;
}

// ---------------------------------------------------------------------------
// Pack kernels
// ---------------------------------------------------------------------------
__global__ __launch_bounds__(256) void pack_x_kernel(const float* __restrict__ x)
{
    size_t idx = (size_t)blockIdx.x * 256 + threadIdx.x;   // float4 index
    float4 v = ((const float4*)x)[idx];
    store_split2(g_xh, g_xl, idx * 4,     v.x, v.y);
    store_split2(g_xh, g_xl, idx * 4 + 2, v.z, v.w);
}

__global__ __launch_bounds__(256) void pack_wt_kernel(
    const float* __restrict__ wq, const float* __restrict__ wk,
    const float* __restrict__ wv, const float* __restrict__ wo)
{
    const int mat = blockIdx.z;
    const float* W = (mat == 0) ? wq : (mat == 1) ? wk : (mat == 2) ? wv : wo;
    __shared__ float s[32][33];
    const int k0 = blockIdx.y * 32, n0 = blockIdx.x * 32;
    const int tx = threadIdx.x & 31, ty = threadIdx.x >> 5;
#pragma unroll
    for (int i = 0; i < 32; i += 8)
        s[ty + i][tx] = W[(size_t)(k0 + ty + i) * EE + n0 + tx];
    __syncthreads();
    __nv_bfloat16* dh = g_wth + (size_t)mat * EE * EE;
    __nv_bfloat16* dl = g_wtl + (size_t)mat * EE * EE;
#pragma unroll
    for (int i = 0; i < 32; i += 8) {
        __nv_bfloat16 h, l;
        split_bf16(s[tx][ty + i], h, l);
        size_t di = (size_t)(n0 + ty + i) * EE + k0 + tx;
        dh[di] = h;
        dl[di] = l;
    }
}

// ---------------------------------------------------------------------------
// cp.async tile loaders
// ---------------------------------------------------------------------------
// GEMM-style: A rows m0.., B rows n0.., both with row stride EE, k offset kelem
__device__ __forceinline__ void cpload_ab(
    uint32_t base, const __nv_bfloat16* Ah, const __nv_bfloat16* Al,
    const __nv_bfloat16* Bh, const __nv_bfloat16* Bl,
    int arow0, int brow0, int kelem, int tid)
{
    const int r = tid >> 2;              // 0..63
    const int kc = tid & 3;              // 16B chunk in 32-k row
    const uint32_t so = (uint32_t)(r * ROWB + kc * 16);
    const size_t go = (size_t)kelem + kc * 8;
#pragma unroll
    for (int half = 0; half < 2; half++) {
        const int row = r + half * 64;
        const uint32_t ho = so + (uint32_t)(half * 64 * ROWB);
        CP16(base + AHI + ho, Ah + (size_t)(arow0 + row) * EE + go);
        CP16(base + ALO + ho, Al + (size_t)(arow0 + row) * EE + go);
        CP16(base + BHI + ho, Bh + (size_t)(brow0 + row) * EE + go);
        CP16(base + BLO + ho, Bl + (size_t)(brow0 + row) * EE + go);
    }
}

// ---------------------------------------------------------------------------
// Warp-tile compute (shared by gemm/logits): 2 ks steps of k=16
// ---------------------------------------------------------------------------
__device__ __forceinline__ void compute_block_128(
    uint32_t base, uint32_t aoff0, uint32_t aoff1, const uint32_t* boff,
    float acc[2][8][4])
{
#pragma unroll
    for (int ks = 0; ks < 2; ks++) {
        const uint32_t ko = (uint32_t)ks * 32;
        uint32_t ah0[4], ah1[4], al0[4], al1[4];
        LDSM4(ah0, base + AHI + aoff0 + ko);
        LDSM4(ah1, base + AHI + aoff1 + ko);
        LDSM4(al0, base + ALO + aoff0 + ko);
        LDSM4(al1, base + ALO + aoff1 + ko);
#pragma unroll
        for (int np = 0; np < 4; np++) {
            uint32_t bh[4], bl[4];
            LDSM4(bh, base + BHI + boff[np] + ko);
            LDSM4(bl, base + BLO + boff[np] + ko);
            mma_bf16(acc[0][np * 2],     ah0, bh[0], bh[1]);
            mma_bf16(acc[0][np * 2],     ah0, bl[0], bl[1]);
            mma_bf16(acc[0][np * 2],     al0, bh[0], bh[1]);
            mma_bf16(acc[0][np * 2 + 1], ah0, bh[2], bh[3]);
            mma_bf16(acc[0][np * 2 + 1], ah0, bl[2], bl[3]);
            mma_bf16(acc[0][np * 2 + 1], al0, bh[2], bh[3]);
            mma_bf16(acc[1][np * 2],     ah1, bh[0], bh[1]);
            mma_bf16(acc[1][np * 2],     ah1, bl[0], bl[1]);
            mma_bf16(acc[1][np * 2],     al1, bh[0], bh[1]);
            mma_bf16(acc[1][np * 2 + 1], ah1, bh[2], bh[3]);
            mma_bf16(acc[1][np * 2 + 1], ah1, bl[2], bl[3]);
            mma_bf16(acc[1][np * 2 + 1], al1, bh[2], bh[3]);
        }
    }
}

// ---------------------------------------------------------------------------
// Stages 1 & 5: dense GEMM. out = (A @ Bt^T + bias) * scale
// PACK: write split planes (Ch, Cl). else: write fp32 (Ch).
// ---------------------------------------------------------------------------
template<bool PACK>
__device__ void gemm_mma_body(
    const __nv_bfloat16* __restrict__ Ah, const __nv_bfloat16* __restrict__ Al,
    const __nv_bfloat16* __restrict__ Bh, const __nv_bfloat16* __restrict__ Bl,
    const float* __restrict__ bias, void* __restrict__ Cout0, void* __restrict__ Cout1,
    float scale, int m0, int n0)
{
    extern __shared__ char smem[];
    const uint32_t sb = smem_to_u32(smem);
    const int tid  = threadIdx.x;
    const int lane = tid & 31;
    const int w    = tid >> 5;
    const int wy   = w & 3;
    const int wx   = w >> 2;

    const uint32_t aoff0 = (uint32_t)((wy * 32 + (lane & 15)) * ROWB + ((lane >> 4) * 8) * 2);
    const uint32_t aoff1 = aoff0 + 16 * ROWB;
    const uint32_t brow  = (uint32_t)(wx * 64 + ((lane >> 4) & 1) * 8 + (lane & 7));
    const uint32_t bkc   = (uint32_t)(((lane >> 3) & 1) * 8) * 2;
    uint32_t boff[4];
#pragma unroll
    for (int np = 0; np < 4; np++)
        boff[np] = (brow + np * 16) * ROWB + bkc;

    float acc[2][8][4];
#pragma unroll
    for (int mi = 0; mi < 2; mi++)
#pragma unroll
        for (int nf = 0; nf < 8; nf++)
#pragma unroll
            for (int r = 0; r < 4; r++) acc[mi][nf][r] = 0.0f;

    cpload_ab(sb, Ah, Al, Bh, Bl, m0, n0, 0, tid);
    CPCOMMIT();
    CPWAIT0();
    __syncthreads();

#pragma unroll 1
    for (int kb = 0; kb < NKB; kb++) {
        if (kb + 1 < NKB) {
            cpload_ab(sb + (uint32_t)((kb + 1) & 1) * BUF_B,
                      Ah, Al, Bh, Bl, m0, n0, (kb + 1) * BK, tid);
            CPCOMMIT();
        }
        compute_block_128(sb + (uint32_t)(kb & 1) * BUF_B, aoff0, aoff1, boff, acc);
        if (kb + 1 < NKB) {
            CPWAIT0();
            __syncthreads();
        }
    }

    const int mbase = m0 + wy * 32 + (lane >> 2);
    const int nbase = n0 + wx * 64 + (lane & 3) * 2;
    float2 bb[8];
#pragma unroll
    for (int nf = 0; nf < 8; nf++)
        bb[nf] = *(const float2*)(bias + nbase + nf * 8);

#pragma unroll
    for (int mi = 0; mi < 2; mi++) {
#pragma unroll
        for (int rr = 0; rr < 2; rr++) {
            const int m = mbase + mi * 16 + rr * 8;
#pragma unroll
            for (int nf = 0; nf < 8; nf++) {
                float v0 = (acc[mi][nf][rr * 2]     + bb[nf].x) * scale;
                float v1 = (acc[mi][nf][rr * 2 + 1] + bb[nf].y) * scale;
                size_t idx = (size_t)m * EE + nbase + nf * 8;
                if (PACK) {
                    store_split2((__nv_bfloat16*)Cout0, (__nv_bfloat16*)Cout1, idx, v0, v1);
                } else {
                    float2 v; v.x = v0; v.y = v1;
                    *(float2*)((float*)Cout0 + idx) = v;
                }
            }
        }
    }
}

__global__ __launch_bounds__(256, 2) void qkv_mma_kernel(
    const float* __restrict__ bq, const float* __restrict__ bk,
    const float* __restrict__ bv)
{
    const int which = blockIdx.z;
    const __nv_bfloat16* Bh = g_wth + (size_t)which * EE * EE;
    const __nv_bfloat16* Bl = g_wtl + (size_t)which * EE * EE;
    const float* bias = (which == 0) ? bq : (which == 1) ? bk : bv;
    __nv_bfloat16* oh = (which == 0) ? g_qh : (which == 1) ? g_kh : g_vh;
    __nv_bfloat16* ol = (which == 0) ? g_ql : (which == 1) ? g_kl : g_vl;
    const float scale = (which == 0) ? QSCALE : 1.0f;
    gemm_mma_body<true>(g_xh, g_xl, Bh, Bl, bias, oh, ol, scale,
                        blockIdx.y * BM, blockIdx.x * BN);
}

__global__ __launch_bounds__(256, 2) void out_mma_kernel(
    const float* __restrict__ bo, float* __restrict__ out)
{
    gemm_mma_body<false>(g_ch, g_cl, g_wth + (size_t)3 * EE * EE,
                         g_wtl + (size_t)3 * EE * EE, bo, out, nullptr, 1.0f,
                         blockIdx.y * BM, blockIdx.x * BN);
}

// ---------------------------------------------------------------------------
// Stage 2: tied-row logits, split-K over r. grid = (4, HH, RSPLIT)
// ---------------------------------------------------------------------------
__global__ __launch_bounds__(256, 2) void logits_mma_kernel()
{
    const int h  = blockIdx.y;
    const int r0 = blockIdx.z * RCHUNK;
    const int m0 = (blockIdx.x >> 1) * 128;
    const int n0 = (blockIdx.x & 1) * 128;
    const int NKK = RCHUNK * 2;               // 32 k-blocks of 32

    extern __shared__ char smem[];
    const uint32_t sb = smem_to_u32(smem);
    const int tid  = threadIdx.x;
    const int lane = tid & 31;
    const int w    = tid >> 5;
    const int wy   = w & 3;
    const int wx   = w >> 2;

    const uint32_t aoff0 = (uint32_t)((wy * 32 + (lane & 15)) * ROWB + ((lane >> 4) * 8) * 2);
    const uint32_t aoff1 = aoff0 + 16 * ROWB;
    const uint32_t brow  = (uint32_t)(wx * 64 + ((lane >> 4) & 1) * 8 + (lane & 7));
    const uint32_t bkc   = (uint32_t)(((lane >> 3) & 1) * 8) * 2;
    uint32_t boff[4];
#pragma unroll
    for (int np = 0; np < 4; np++)
        boff[np] = (brow + np * 16) * ROWB + bkc;

    float acc[2][8][4];
#pragma unroll
    for (int mi = 0; mi < 2; mi++)
#pragma unroll
        for (int nf = 0; nf < 8; nf++)
#pragma unroll
            for (int r = 0; r < 4; r++) acc[mi][nf][r] = 0.0f;

    // k-block kk: row base r0+(kk>>1), k elems h*64 + (kk&1)*32
    cpload_ab(sb, g_qh, g_ql, g_kh, g_kl,
              r0 * CC + m0, r0 * CC + n0, h * DD, tid);
    CPCOMMIT();
    CPWAIT0();
    __syncthreads();

#pragma unroll 1
    for (int kk = 0; kk < NKK; kk++) {
        if (kk + 1 < NKK) {
            const int rr_ = r0 + ((kk + 1) >> 1);
            const int ke  = h * DD + ((kk + 1) & 1) * 32;
            cpload_ab(sb + (uint32_t)((kk + 1) & 1) * BUF_B,
                      g_qh, g_ql, g_kh, g_kl,
                      rr_ * CC + m0, rr_ * CC + n0, ke, tid);
            CPCOMMIT();
        }
        compute_block_128(sb + (uint32_t)(kk & 1) * BUF_B, aoff0, aoff1, boff, acc);
        if (kk + 1 < NKK) {
            CPWAIT0();
            __syncthreads();
        }
    }

    float* P = g_lpart + ((size_t)blockIdx.z * HH + h) * CC * CC;
    const int mbase = m0 + wy * 32 + (lane >> 2);
    const int nbase = n0 + wx * 64 + (lane & 3) * 2;
#pragma unroll
    for (int mi = 0; mi < 2; mi++) {
#pragma unroll
        for (int rr = 0; rr < 2; rr++) {
            const int m = mbase + mi * 16 + rr * 8;
#pragma unroll
            for (int nf = 0; nf < 8; nf++) {
                float2 v;
                v.x = acc[mi][nf][rr * 2];
                v.y = acc[mi][nf][rr * 2 + 1];
                *(float2*)(P + (size_t)m * CC + nbase + nf * 8) = v;
            }
        }
    }
}

// ---------------------------------------------------------------------------
// Stage 3: split-K reduce + softmax + split-pack. grid = HH*CC
// ---------------------------------------------------------------------------
__global__ __launch_bounds__(256) void softmax_kernel()
{
    const size_t row = blockIdx.x;
    const int t = threadIdx.x;
    __shared__ float red[256];

    float v = 0.0f;
#pragma unroll
    for (int rs = 0; rs < RSPLIT; rs++)
        v += g_lpart[((size_t)rs * HH * CC + row) * CC + t];

    red[t] = v;
    __syncthreads();
#pragma unroll
    for (int s = 128; s > 0; s >>= 1) {
        if (t < s) red[t] = fmaxf(red[t], red[t + s]);
        __syncthreads();
    }
    const float m = red[0];
    __syncthreads();

    const float e = __expf(v - m);
    red[t] = e;
    __syncthreads();
#pragma unroll
    for (int s = 128; s > 0; s >>= 1) {
        if (t < s) red[t] += red[t + s];
        __syncthreads();
    }
    const float p = e / red[0];
    __nv_bfloat16 h, l;
    split_bf16(p, h, l);
    g_ph[row * CC + t] = h;
    g_pl[row * CC + t] = l;
}

// ---------------------------------------------------------------------------
// Stage 4: context. ctx[r,i,h,d] = sum_j P[h,i,j]*v[r,j,h,d]
// grid = (2, RR, HH). CTA: 128(i) x 64(d) x 256(j).
// ---------------------------------------------------------------------------
__global__ __launch_bounds__(256, 2) void context_mma_kernel()
{
    const int h  = blockIdx.z;
    const int r  = blockIdx.y;
    const int i0 = blockIdx.x * 128;
    const int NJB = CC / BK;           // 8

    extern __shared__ char smem[];
    const uint32_t sb = smem_to_u32(smem);
    const int tid  = threadIdx.x;
    const int lane = tid & 31;
    const int w    = tid >> 5;
    const int wy   = w & 3;
    const int wx   = w >> 2;

    const __nv_bfloat16* Ph = g_ph + (size_t)h * CC * CC;
    const __nv_bfloat16* Pl = g_pl + (size_t)h * CC * CC;

    const uint32_t aoff0 = (uint32_t)((wy * 32 + (lane & 15)) * ROWB + ((lane >> 4) * 8) * 2);
    const uint32_t aoff1 = aoff0 + 16 * ROWB;
    const uint32_t mi_ = (uint32_t)(lane >> 3);
    const uint32_t wi_ = (uint32_t)(lane & 7);
    const uint32_t vlb = ((mi_ & 1) * 8 + wi_) * VROWB + ((mi_ >> 1) * 8) * 2 + (uint32_t)(wx * 32) * 2;

    float acc[2][4][4];
#pragma unroll
    for (int mi = 0; mi < 2; mi++)
#pragma unroll
        for (int nf = 0; nf < 4; nf++)
#pragma unroll
            for (int q = 0; q < 4; q++) acc[mi][nf][q] = 0.0f;

    // loader: P tiles (128 rows x 32 j) + V tiles (32 j x 64 d)
    const int pr = tid >> 2, pc = tid & 3;       // P: rows 0..63 (+64), chunks
    const int vr = tid >> 3, vc = tid & 7;       // V: rows 0..31, 8 chunks
    auto cpload_ctx = [&](uint32_t base, int jb) {
        const uint32_t so = (uint32_t)(pr * ROWB + pc * 16);
        const size_t pgo = (size_t)jb * 32 + pc * 8;
#pragma unroll
        for (int half = 0; half < 2; half++) {
            const int row = pr + half * 64;
            const uint32_t ho = so + (uint32_t)(half * 64 * ROWB);
            CP16(base + CPHI + ho, Ph + (size_t)(i0 + row) * CC + pgo);
            CP16(base + CPLO + ho, Pl + (size_t)(i0 + row) * CC + pgo);
        }
        const uint32_t sv = (uint32_t)(vr * VROWB + vc * 16);
        const size_t vgo = (size_t)(r * CC + jb * 32 + vr) * EE + h * DD + vc * 8;
        CP16(base + CVHI + sv, g_vh + vgo);
        CP16(base + CVLO + sv, g_vl + vgo);
    };

    cpload_ctx(sb, 0);
    CPCOMMIT();
    CPWAIT0();
    __syncthreads();

#pragma unroll 1
    for (int jb = 0; jb < NJB; jb++) {
        if (jb + 1 < NJB) {
            cpload_ctx(sb + (uint32_t)((jb + 1) & 1) * CBUF_B, jb + 1);
            CPCOMMIT();
        }

        const uint32_t base = sb + (uint32_t)(jb & 1) * CBUF_B;
#pragma unroll
        for (int ks = 0; ks < 2; ks++) {
            const uint32_t ko = (uint32_t)ks * 32;
            const uint32_t kv = (uint32_t)ks * 16 * VROWB;
            uint32_t ah0[4], ah1[4], al0[4], al1[4];
            LDSM4(ah0, base + CPHI + aoff0 + ko);
            LDSM4(ah1, base + CPHI + aoff1 + ko);
            LDSM4(al0, base + CPLO + aoff0 + ko);
            LDSM4(al1, base + CPLO + aoff1 + ko);
#pragma unroll
            for (int np = 0; np < 2; np++) {
                uint32_t bh[4], bl[4];
                const uint32_t va = vlb + kv + (uint32_t)(np * 16) * 2;
                LDSM4T(bh, base + CVHI + va);
                LDSM4T(bl, base + CVLO + va);
                mma_bf16(acc[0][np * 2],     ah0, bh[0], bh[1]);
                mma_bf16(acc[0][np * 2],     ah0, bl[0], bl[1]);
                mma_bf16(acc[0][np * 2],     al0, bh[0], bh[1]);
                mma_bf16(acc[0][np * 2 + 1], ah0, bh[2], bh[3]);
                mma_bf16(acc[0][np * 2 + 1], ah0, bl[2], bl[3]);
                mma_bf16(acc[0][np * 2 + 1], al0, bh[2], bh[3]);
                mma_bf16(acc[1][np * 2],     ah1, bh[0], bh[1]);
                mma_bf16(acc[1][np * 2],     ah1, bl[0], bl[1]);
                mma_bf16(acc[1][np * 2],     al1, bh[0], bh[1]);
                mma_bf16(acc[1][np * 2 + 1], ah1, bh[2], bh[3]);
                mma_bf16(acc[1][np * 2 + 1], ah1, bl[2], bl[3]);
                mma_bf16(acc[1][np * 2 + 1], al1, bh[2], bh[3]);
            }
        }

        if (jb + 1 < NJB) {
            CPWAIT0();
            __syncthreads();
        }
    }

    const int mbase = i0 + wy * 32 + (lane >> 2);
    const int dbase = wx * 32 + (lane & 3) * 2;
#pragma unroll
    for (int mi = 0; mi < 2; mi++) {
#pragma unroll
        for (int rr = 0; rr < 2; rr++) {
            const int i = mbase + mi * 16 + rr * 8;
            size_t rowo = (size_t)(r * CC + i) * EE + h * DD;
#pragma unroll
            for (int nf = 0; nf < 4; nf++) {
                store_split2(g_ch, g_cl, rowo + dbase + nf * 8,
                             acc[mi][nf][rr * 2], acc[mi][nf][rr * 2 + 1]);
            }
        }
    }
}

// ---------------------------------------------------------------------------
extern "C" void kernel_launch(void* const* d_in, const int* in_sizes, int n_in,
                              void* d_out, int out_size)
{
    (void)in_sizes; (void)n_in; (void)out_size;
    const float* x  = (const float*)d_in[0];
    const float* wq = (const float*)d_in[1];
    const float* bq = (const float*)d_in[2];
    const float* wk = (const float*)d_in[3];
    const float* bk = (const float*)d_in[4];
    const float* wv = (const float*)d_in[5];
    const float* bv = (const float*)d_in[6];
    const float* wo = (const float*)d_in[7];
    const float* bo = (const float*)d_in[8];
    float* out = (float*)d_out;

    static int smem_configured = 0;
    if (!smem_configured) {
        cudaFuncSetAttribute(qkv_mma_kernel,
                             cudaFuncAttributeMaxDynamicSharedMemorySize, SMEM_TOTAL);
        cudaFuncSetAttribute(out_mma_kernel,
                             cudaFuncAttributeMaxDynamicSharedMemorySize, SMEM_TOTAL);
        cudaFuncSetAttribute(logits_mma_kernel,
                             cudaFuncAttributeMaxDynamicSharedMemorySize, SMEM_TOTAL);
        cudaFuncSetAttribute(context_mma_kernel,
                             cudaFuncAttributeMaxDynamicSharedMemorySize, CSMEM_TOTAL);
        smem_configured = 1;
    }

    pack_x_kernel<<<(MTOK * EE / 4) / 256, 256>>>(x);
    dim3 gw(EE / 32, EE / 32, 4);
    pack_wt_kernel<<<gw, 256>>>(wq, wk, wv, wo);

    dim3 g1(EE / BN, MTOK / BM, 3);               // (6, 256, 3)
    qkv_mma_kernel<<<g1, 256, SMEM_TOTAL>>>(bq, bk, bv);

    dim3 g2(4, HH, RSPLIT);                       // 384 CTAs
    logits_mma_kernel<<<g2, 256, SMEM_TOTAL>>>();

    softmax_kernel<<<HH * CC, 256>>>();

    dim3 g4(CC / BM, RR, HH);                     // 3072 CTAs
    context_mma_kernel<<<g4, 256, CSMEM_TOTAL>>>();

    dim3 g5(EE / BN, MTOK / BM, 1);               // (6, 256)
    out_mma_kernel<<<g5, 256, SMEM_TOTAL>>>(bo, out);
}

// round 12
// speedup vs baseline: 1.1481x; 1.1481x over previous
#include <cuda_runtime.h>
#include <cuda_bf16.h>
#include <stdint.h>
#include <math.h>

// ---------------------------------------------------------------------------
// Problem constants
// ---------------------------------------------------------------------------
#define RR 128
#define CC 256
#define EE 768
#define HH 12
#define DD 64
#define MTOK (RR * CC)            // 32768 tokens
#define QSCALE (0.0110485434560398f)   // (1/8) / sqrt(128)
#define RSPLIT 16
#define RCHUNK (RR / RSPLIT)      // 8

// ---------------------------------------------------------------------------
// Dense/logits tiling: CTA 128x128, BK=32, 8 warps (4M x 2N)
// Swizzled 64B smem rows, 3-stage cp.async pipeline, 2 CTAs/SM.
// ---------------------------------------------------------------------------
#define BM 128
#define BN 128
#define BK 32
#define NKB (EE / BK)             // 24
#define SROW 64                   // bytes per smem row (32 bf16), swizzled
#define PTILE (128 * SROW)        // 8192 bytes per plane tile
#define ST_AHI 0
#define ST_ALO PTILE
#define ST_BHI (2 * PTILE)
#define ST_BLO (3 * PTILE)
#define STAGE_B (4 * PTILE)       // 32768
#define NSTAGE 3
#define GSMEM (NSTAGE * STAGE_B)  // 98304

// context kernel smem (unchanged padded layout, double buffer)
#define ROWB 80
#define VROWB 144
#define CPTILE (128 * ROWB)
#define CVTILE (32 * VROWB)
#define CPHI 0
#define CPLO CPTILE
#define CVHI (2 * CPTILE)
#define CVLO (2 * CPTILE + CVTILE)
#define CBUF_B (2 * CPTILE + 2 * CVTILE)
#define CSMEM_TOTAL (2 * CBUF_B)

// ---------------------------------------------------------------------------
// Device global scratch: separate hi / lo bf16 planes
// ---------------------------------------------------------------------------
__device__ __nv_bfloat16 g_xh[(size_t)MTOK * EE], g_xl[(size_t)MTOK * EE];
__device__ __nv_bfloat16 g_wth[4 * (size_t)EE * EE], g_wtl[4 * (size_t)EE * EE];
__device__ __nv_bfloat16 g_qh[(size_t)MTOK * EE],  g_ql[(size_t)MTOK * EE];
__device__ __nv_bfloat16 g_kh[(size_t)MTOK * EE],  g_kl[(size_t)MTOK * EE];
__device__ __nv_bfloat16 g_vh[(size_t)MTOK * EE],  g_vl[(size_t)MTOK * EE];
__device__ __nv_bfloat16 g_ch[(size_t)MTOK * EE],  g_cl[(size_t)MTOK * EE];
__device__ __nv_bfloat16 g_ph[(size_t)HH * CC * CC], g_pl[(size_t)HH * CC * CC];
__device__ float         g_lpart[(size_t)RSPLIT * HH * CC * CC];

// ---------------------------------------------------------------------------
// Helpers
// ---------------------------------------------------------------------------
__device__ __forceinline__ uint32_t smem_to_u32(const void* p) {
    uint32_t a;
    asm("{ .reg .u64 t; cvta.to.shared.u64 t, %1; cvt.u32.u64 %0, t; }"
        : "=r"(a) : "l"(p));
    return a;
}

#define CP16(saddr, gptr) \
    asm volatile("cp.async.cg.shared.global [%0], [%1], 16;" \
        :: "r"(saddr), "l"(gptr) : "memory")
#define CPCOMMIT() asm volatile("cp.async.commit_group;" ::: "memory")
#define CPWAIT0()  asm volatile("cp.async.wait_group 0;" ::: "memory")
#define CPWAIT1()  asm volatile("cp.async.wait_group 1;" ::: "memory")

#define LDSM4(r, addr) \
    asm volatile("ldmatrix.sync.aligned.m8n8.x4.shared.b16 {%0,%1,%2,%3}, [%4];" \
        : "=r"((r)[0]), "=r"((r)[1]), "=r"((r)[2]), "=r"((r)[3]) : "r"(addr))

#define LDSM4T(r, addr) \
    asm volatile("ldmatrix.sync.aligned.m8n8.x4.trans.shared.b16 {%0,%1,%2,%3}, [%4];" \
        : "=r"((r)[0]), "=r"((r)[1]), "=r"((r)[2]), "=r"((r)[3]) : "r"(addr))

__device__ __forceinline__ void mma_bf16(float* c, const uint32_t* a,
                                         uint32_t b0, uint32_t b1) {
    asm volatile(
        "mma.sync.aligned.m16n8k16.row.col.f32.bf16.bf16.f32 "
        "{%0,%1,%2,%3}, {%4,%5,%6,%7}, {%8,%9}, {%0,%1,%2,%3};"
        : "+f"(c[0]), "+f"(c[1]), "+f"(c[2]), "+f"(c[3])
        : "r"(a[0]), "r"(a[1]), "r"(a[2]), "r"(a[3]), "r"(b0), "r"(b1));
}

__device__ __forceinline__ void split_bf16(float f, __nv_bfloat16& h, __nv_bfloat16& l) {
    h = __float2bfloat16(f);
    l = __float2bfloat16(f - __bfloat162float(h));
}

__device__ __forceinline__ void store_split2(
    __nv_bfloat16* Ph, __nv_bfloat16* Pl, size_t idx, float v0, float v1)
{
    __nv_bfloat16 h0, l0, h1, l1;
    split_bf16(v0, h0, l0);
    split_bf16(v1, h1, l1);
    uint32_t uh = (uint32_t)__bfloat16_as_ushort(h0) | ((uint32_t)__bfloat16_as_ushort(h1) << 16);
    uint32_t ul = (uint32_t)__bfloat16_as_ushort(l0) | ((uint32_t)__bfloat16_as_ushort(l1) << 16);
    *(uint32_t*)(Ph + idx) = uh;
    *(uint32_t*)(Pl + idx) = ul;
}

// swizzled smem address: 64B rows, 4 chunks of 16B, chunk ^= (row>>1)&3
__device__ __forceinline__ uint32_t swz(int row, int chunk) {
    return (uint32_t)(row * SROW) + (uint32_t)(((chunk ^ ((row >> 1) & 3)) << 4));
}

// ---------------------------------------------------------------------------
// Pack kernels
// ---------------------------------------------------------------------------
__global__ __launch_bounds__(256) void pack_x_kernel(const float* __restrict__ x)
{
    size_t idx = (size_t)blockIdx.x * 256 + threadIdx.x;
    float4 v = ((const float4*)x)[idx];
    store_split2(g_xh, g_xl, idx * 4,     v.x, v.y);
    store_split2(g_xh, g_xl, idx * 4 + 2, v.z, v.w);
}

__global__ __launch_bounds__(256) void pack_wt_kernel(
    const float* __restrict__ wq, const float* __restrict__ wk,
    const float* __restrict__ wv, const float* __restrict__ wo)
{
    const int mat = blockIdx.z;
    const float* W = (mat == 0) ? wq : (mat == 1) ? wk : (mat == 2) ? wv : wo;
    __shared__ float s[32][33];
    const int k0 = blockIdx.y * 32, n0 = blockIdx.x * 32;
    const int tx = threadIdx.x & 31, ty = threadIdx.x >> 5;
#pragma unroll
    for (int i = 0; i < 32; i += 8)
        s[ty + i][tx] = W[(size_t)(k0 + ty + i) * EE + n0 + tx];
    __syncthreads();
    __nv_bfloat16* dh = g_wth + (size_t)mat * EE * EE;
    __nv_bfloat16* dl = g_wtl + (size_t)mat * EE * EE;
#pragma unroll
    for (int i = 0; i < 32; i += 8) {
        __nv_bfloat16 h, l;
        split_bf16(s[tx][ty + i], h, l);
        size_t di = (size_t)(n0 + ty + i) * EE + k0 + tx;
        dh[di] = h;
        dl[di] = l;
    }
}

// ---------------------------------------------------------------------------
// Fragment addressing (per-lane, precomputed)
// ---------------------------------------------------------------------------
struct Frag {
    uint32_t arb0, arb1;      // A row byte bases (mi=0,1)
    uint32_t axr0, axr1;      // A row xor masks
    uint32_t brb[4], bxr[4];  // B row bases / xors (np=0..3)
    uint32_t acs, bcs;        // A/B base chunk select
};

__device__ __forceinline__ Frag make_frag(int lane, int wy, int wx) {
    Frag f;
    const int ar0 = wy * 32 + (lane & 15);
    const int ar1 = ar0 + 16;
    f.arb0 = (uint32_t)(ar0 * SROW); f.axr0 = (uint32_t)((ar0 >> 1) & 3);
    f.arb1 = (uint32_t)(ar1 * SROW); f.axr1 = (uint32_t)((ar1 >> 1) & 3);
    const int br = wx * 64 + ((lane >> 4) & 1) * 8 + (lane & 7);
#pragma unroll
    for (int np = 0; np < 4; np++) {
        const int r = br + np * 16;
        f.brb[np] = (uint32_t)(r * SROW);
        f.bxr[np] = (uint32_t)((r >> 1) & 3);
    }
    f.acs = (uint32_t)(lane >> 4);         // 0 or 1
    f.bcs = (uint32_t)((lane >> 3) & 1);   // 0 or 1
    return f;
}

__device__ __forceinline__ void compute_block(
    uint32_t base, const Frag& f, float acc[2][8][4])
{
#pragma unroll
    for (int ks = 0; ks < 2; ks++) {
        const uint32_t ca = f.acs + (uint32_t)(ks * 2);
        uint32_t ah0[4], ah1[4], al0[4], al1[4];
        LDSM4(ah0, base + ST_AHI + f.arb0 + ((ca ^ f.axr0) << 4));
        LDSM4(ah1, base + ST_AHI + f.arb1 + ((ca ^ f.axr1) << 4));
        LDSM4(al0, base + ST_ALO + f.arb0 + ((ca ^ f.axr0) << 4));
        LDSM4(al1, base + ST_ALO + f.arb1 + ((ca ^ f.axr1) << 4));
        const uint32_t cb = f.bcs + (uint32_t)(ks * 2);
#pragma unroll
        for (int np = 0; np < 4; np++) {
            uint32_t bh[4], bl[4];
            const uint32_t bo = ((cb ^ f.bxr[np]) << 4);
            LDSM4(bh, base + ST_BHI + f.brb[np] + bo);
            LDSM4(bl, base + ST_BLO + f.brb[np] + bo);
            mma_bf16(acc[0][np * 2],     ah0, bh[0], bh[1]);
            mma_bf16(acc[0][np * 2],     ah0, bl[0], bl[1]);
            mma_bf16(acc[0][np * 2],     al0, bh[0], bh[1]);
            mma_bf16(acc[0][np * 2 + 1], ah0, bh[2], bh[3]);
            mma_bf16(acc[0][np * 2 + 1], ah0, bl[2], bl[3]);
            mma_bf16(acc[0][np * 2 + 1], al0, bh[2], bh[3]);
            mma_bf16(acc[1][np * 2],     ah1, bh[0], bh[1]);
            mma_bf16(acc[1][np * 2],     ah1, bl[0], bl[1]);
            mma_bf16(acc[1][np * 2],     al1, bh[0], bh[1]);
            mma_bf16(acc[1][np * 2 + 1], ah1, bh[2], bh[3]);
            mma_bf16(acc[1][np * 2 + 1], ah1, bl[2], bl[3]);
            mma_bf16(acc[1][np * 2 + 1], al1, bh[2], bh[3]);
        }
    }
}

// loader: A rows arow0.., B rows brow0.., k offset kelem (both stride EE)
__device__ __forceinline__ void cpload_ab(
    uint32_t base, const __nv_bfloat16* Ah, const __nv_bfloat16* Al,
    const __nv_bfloat16* Bh, const __nv_bfloat16* Bl,
    int arow0, int brow0, int kelem, int tid)
{
    const int r = tid >> 2;              // 0..63
    const int kc = tid & 3;              // 16B chunk
    const size_t go = (size_t)kelem + kc * 8;
#pragma unroll
    for (int half = 0; half < 2; half++) {
        const int row = r + half * 64;
        const uint32_t so = swz(row, kc);
        CP16(base + ST_AHI + so, Ah + (size_t)(arow0 + row) * EE + go);
        CP16(base + ST_ALO + so, Al + (size_t)(arow0 + row) * EE + go);
        CP16(base + ST_BHI + so, Bh + (size_t)(brow0 + row) * EE + go);
        CP16(base + ST_BLO + so, Bl + (size_t)(brow0 + row) * EE + go);
    }
}

// ---------------------------------------------------------------------------
// Stages 1 & 5: dense GEMM. out = (A @ Bt^T + bias) * scale
// ---------------------------------------------------------------------------
template<bool PACK>
__device__ void gemm_mma_body(
    const __nv_bfloat16* __restrict__ Ah, const __nv_bfloat16* __restrict__ Al,
    const __nv_bfloat16* __restrict__ Bh, const __nv_bfloat16* __restrict__ Bl,
    const float* __restrict__ bias, void* __restrict__ Cout0, void* __restrict__ Cout1,
    float scale, int m0, int n0)
{
    extern __shared__ char smem[];
    const uint32_t sb = smem_to_u32(smem);
    const int tid  = threadIdx.x;
    const int lane = tid & 31;
    const int w    = tid >> 5;
    const int wy   = w & 3;
    const int wx   = w >> 2;
    const Frag f = make_frag(lane, wy, wx);

    float acc[2][8][4];
#pragma unroll
    for (int mi = 0; mi < 2; mi++)
#pragma unroll
        for (int nf = 0; nf < 8; nf++)
#pragma unroll
            for (int r = 0; r < 4; r++) acc[mi][nf][r] = 0.0f;

    cpload_ab(sb, Ah, Al, Bh, Bl, m0, n0, 0, tid);
    CPCOMMIT();
    cpload_ab(sb + STAGE_B, Ah, Al, Bh, Bl, m0, n0, BK, tid);
    CPCOMMIT();

    uint32_t bufo[3] = {sb, sb + STAGE_B, sb + 2 * STAGE_B};
#pragma unroll 1
    for (int kb = 0; kb < NKB; kb++) {
        if (kb == NKB - 1) { CPWAIT0(); } else { CPWAIT1(); }
        __syncthreads();
        compute_block(bufo[kb % 3], f, acc);
        if (kb + 2 < NKB) {
            cpload_ab(bufo[(kb + 2) % 3], Ah, Al, Bh, Bl, m0, n0, (kb + 2) * BK, tid);
            CPCOMMIT();
        }
    }

    const int mbase = m0 + wy * 32 + (lane >> 2);
    const int nbase = n0 + wx * 64 + (lane & 3) * 2;
    float2 bb[8];
#pragma unroll
    for (int nf = 0; nf < 8; nf++)
        bb[nf] = *(const float2*)(bias + nbase + nf * 8);

#pragma unroll
    for (int mi = 0; mi < 2; mi++) {
#pragma unroll
        for (int rr = 0; rr < 2; rr++) {
            const int m = mbase + mi * 16 + rr * 8;
#pragma unroll
            for (int nf = 0; nf < 8; nf++) {
                float v0 = (acc[mi][nf][rr * 2]     + bb[nf].x) * scale;
                float v1 = (acc[mi][nf][rr * 2 + 1] + bb[nf].y) * scale;
                size_t idx = (size_t)m * EE + nbase + nf * 8;
                if (PACK) {
                    store_split2((__nv_bfloat16*)Cout0, (__nv_bfloat16*)Cout1, idx, v0, v1);
                } else {
                    float2 v; v.x = v0; v.y = v1;
                    *(float2*)((float*)Cout0 + idx) = v;
                }
            }
        }
    }
}

__global__ __launch_bounds__(256, 2) void qkv_mma_kernel(
    const float* __restrict__ bq, const float* __restrict__ bk,
    const float* __restrict__ bv)
{
    const int which = blockIdx.z;
    const __nv_bfloat16* Bh = g_wth + (size_t)which * EE * EE;
    const __nv_bfloat16* Bl = g_wtl + (size_t)which * EE * EE;
    const float* bias = (which == 0) ? bq : (which == 1) ? bk : bv;
    __nv_bfloat16* oh = (which == 0) ? g_qh : (which == 1) ? g_kh : g_vh;
    __nv_bfloat16* ol = (which == 0) ? g_ql : (which == 1) ? g_kl : g_vl;
    const float scale = (which == 0) ? QSCALE : 1.0f;
    gemm_mma_body<true>(g_xh, g_xl, Bh, Bl, bias, oh, ol, scale,
                        blockIdx.y * BM, blockIdx.x * BN);
}

__global__ __launch_bounds__(256, 2) void out_mma_kernel(
    const float* __restrict__ bo, float* __restrict__ out)
{
    gemm_mma_body<false>(g_ch, g_cl, g_wth + (size_t)3 * EE * EE,
                         g_wtl + (size_t)3 * EE * EE, bo, out, nullptr, 1.0f,
                         blockIdx.y * BM, blockIdx.x * BN);
}

// ---------------------------------------------------------------------------
// Stage 2: tied-row logits, split-K over r. grid = (4, HH, RSPLIT)
// k-block kk: rows (r0 + kk/2)*CC + tile, k elems h*64 + (kk&1)*32
// ---------------------------------------------------------------------------
__global__ __launch_bounds__(256, 2) void logits_mma_kernel()
{
    const int h  = blockIdx.y;
    const int r0 = blockIdx.z * RCHUNK;
    const int m0 = (blockIdx.x >> 1) * 128;
    const int n0 = (blockIdx.x & 1) * 128;
    const int NKK = RCHUNK * 2;               // 16

    extern __shared__ char smem[];
    const uint32_t sb = smem_to_u32(smem);
    const int tid  = threadIdx.x;
    const int lane = tid & 31;
    const int w    = tid >> 5;
    const int wy   = w & 3;
    const int wx   = w >> 2;
    const Frag f = make_frag(lane, wy, wx);

    float acc[2][8][4];
#pragma unroll
    for (int mi = 0; mi < 2; mi++)
#pragma unroll
        for (int nf = 0; nf < 8; nf++)
#pragma unroll
            for (int r = 0; r < 4; r++) acc[mi][nf][r] = 0.0f;

    auto arow = [&](int kk) { return (r0 + (kk >> 1)) * CC + m0; };
    auto brow = [&](int kk) { return (r0 + (kk >> 1)) * CC + n0; };
    auto kel  = [&](int kk) { return h * DD + (kk & 1) * 32; };

    cpload_ab(sb, g_qh, g_ql, g_kh, g_kl, arow(0), brow(0), kel(0), tid);
    CPCOMMIT();
    cpload_ab(sb + STAGE_B, g_qh, g_ql, g_kh, g_kl, arow(1), brow(1), kel(1), tid);
    CPCOMMIT();

    uint32_t bufo[3] = {sb, sb + STAGE_B, sb + 2 * STAGE_B};
#pragma unroll 1
    for (int kk = 0; kk < NKK; kk++) {
        if (kk == NKK - 1) { CPWAIT0(); } else { CPWAIT1(); }
        __syncthreads();
        compute_block(bufo[kk % 3], f, acc);
        if (kk + 2 < NKK) {
            cpload_ab(bufo[(kk + 2) % 3], g_qh, g_ql, g_kh, g_kl,
                      arow(kk + 2), brow(kk + 2), kel(kk + 2), tid);
            CPCOMMIT();
        }
    }

    float* P = g_lpart + ((size_t)blockIdx.z * HH + h) * CC * CC;
    const int mbase = m0 + wy * 32 + (lane >> 2);
    const int nbase = n0 + wx * 64 + (lane & 3) * 2;
#pragma unroll
    for (int mi = 0; mi < 2; mi++) {
#pragma unroll
        for (int rr = 0; rr < 2; rr++) {
            const int m = mbase + mi * 16 + rr * 8;
#pragma unroll
            for (int nf = 0; nf < 8; nf++) {
                float2 v;
                v.x = acc[mi][nf][rr * 2];
                v.y = acc[mi][nf][rr * 2 + 1];
                *(float2*)(P + (size_t)m * CC + nbase + nf * 8) = v;
            }
        }
    }
}

// ---------------------------------------------------------------------------
// Stage 3: split-K reduce + softmax + split-pack. grid = HH*CC
// ---------------------------------------------------------------------------
__global__ __launch_bounds__(256) void softmax_kernel()
{
    const size_t row = blockIdx.x;
    const int t = threadIdx.x;
    __shared__ float red[256];

    float v = 0.0f;
#pragma unroll
    for (int rs = 0; rs < RSPLIT; rs++)
        v += g_lpart[((size_t)rs * HH * CC + row) * CC + t];

    red[t] = v;
    __syncthreads();
#pragma unroll
    for (int s = 128; s > 0; s >>= 1) {
        if (t < s) red[t] = fmaxf(red[t], red[t + s]);
        __syncthreads();
    }
    const float m = red[0];
    __syncthreads();

    const float e = __expf(v - m);
    red[t] = e;
    __syncthreads();
#pragma unroll
    for (int s = 128; s > 0; s >>= 1) {
        if (t < s) red[t] += red[t + s];
        __syncthreads();
    }
    const float p = e / red[0];
    __nv_bfloat16 h, l;
    split_bf16(p, h, l);
    g_ph[row * CC + t] = h;
    g_pl[row * CC + t] = l;
}

// ---------------------------------------------------------------------------
// Stage 4: context (unchanged padded double-buffer version).
// ctx[r,i,h,d] = sum_j P[h,i,j]*v[r,j,h,d].  grid = (2, RR, HH)
// ---------------------------------------------------------------------------
__global__ __launch_bounds__(256, 2) void context_mma_kernel()
{
    const int h  = blockIdx.z;
    const int r  = blockIdx.y;
    const int i0 = blockIdx.x * 128;
    const int NJB = CC / BK;           // 8

    extern __shared__ char smem[];
    const uint32_t sb = smem_to_u32(smem);
    const int tid  = threadIdx.x;
    const int lane = tid & 31;
    const int w    = tid >> 5;
    const int wy   = w & 3;
    const int wx   = w >> 2;

    const __nv_bfloat16* Ph = g_ph + (size_t)h * CC * CC;
    const __nv_bfloat16* Pl = g_pl + (size_t)h * CC * CC;

    const uint32_t aoff0 = (uint32_t)((wy * 32 + (lane & 15)) * ROWB + ((lane >> 4) * 8) * 2);
    const uint32_t aoff1 = aoff0 + 16 * ROWB;
    const uint32_t mi_ = (uint32_t)(lane >> 3);
    const uint32_t wi_ = (uint32_t)(lane & 7);
    const uint32_t vlb = ((mi_ & 1) * 8 + wi_) * VROWB + ((mi_ >> 1) * 8) * 2 + (uint32_t)(wx * 32) * 2;

    float acc[2][4][4];
#pragma unroll
    for (int mi = 0; mi < 2; mi++)
#pragma unroll
        for (int nf = 0; nf < 4; nf++)
#pragma unroll
            for (int q = 0; q < 4; q++) acc[mi][nf][q] = 0.0f;

    const int pr = tid >> 2, pc = tid & 3;
    const int vr = tid >> 3, vc = tid & 7;
    auto cpload_ctx = [&](uint32_t base, int jb) {
        const uint32_t so = (uint32_t)(pr * ROWB + pc * 16);
        const size_t pgo = (size_t)jb * 32 + pc * 8;
#pragma unroll
        for (int half = 0; half < 2; half++) {
            const int row = pr + half * 64;
            const uint32_t ho = so + (uint32_t)(half * 64 * ROWB);
            CP16(base + CPHI + ho, Ph + (size_t)(i0 + row) * CC + pgo);
            CP16(base + CPLO + ho, Pl + (size_t)(i0 + row) * CC + pgo);
        }
        const uint32_t sv = (uint32_t)(vr * VROWB + vc * 16);
        const size_t vgo = (size_t)(r * CC + jb * 32 + vr) * EE + h * DD + vc * 8;
        CP16(base + CVHI + sv, g_vh + vgo);
        CP16(base + CVLO + sv, g_vl + vgo);
    };

    cpload_ctx(sb, 0);
    CPCOMMIT();
    CPWAIT0();
    __syncthreads();

#pragma unroll 1
    for (int jb = 0; jb < NJB; jb++) {
        if (jb + 1 < NJB) {
            cpload_ctx(sb + (uint32_t)((jb + 1) & 1) * CBUF_B, jb + 1);
            CPCOMMIT();
        }

        const uint32_t base = sb + (uint32_t)(jb & 1) * CBUF_B;
#pragma unroll
        for (int ks = 0; ks < 2; ks++) {
            const uint32_t ko = (uint32_t)ks * 32;
            const uint32_t kv = (uint32_t)ks * 16 * VROWB;
            uint32_t ah0[4], ah1[4], al0[4], al1[4];
            LDSM4(ah0, base + CPHI + aoff0 + ko);
            LDSM4(ah1, base + CPHI + aoff1 + ko);
            LDSM4(al0, base + CPLO + aoff0 + ko);
            LDSM4(al1, base + CPLO + aoff1 + ko);
#pragma unroll
            for (int np = 0; np < 2; np++) {
                uint32_t bh[4], bl[4];
                const uint32_t va = vlb + kv + (uint32_t)(np * 16) * 2;
                LDSM4T(bh, base + CVHI + va);
                LDSM4T(bl, base + CVLO + va);
                mma_bf16(acc[0][np * 2],     ah0, bh[0], bh[1]);
                mma_bf16(acc[0][np * 2],     ah0, bl[0], bl[1]);
                mma_bf16(acc[0][np * 2],     al0, bh[0], bh[1]);
                mma_bf16(acc[0][np * 2 + 1], ah0, bh[2], bh[3]);
                mma_bf16(acc[0][np * 2 + 1], ah0, bl[2], bl[3]);
                mma_bf16(acc[0][np * 2 + 1], al0, bh[2], bh[3]);
                mma_bf16(acc[1][np * 2],     ah1, bh[0], bh[1]);
                mma_bf16(acc[1][np * 2],     ah1, bl[0], bl[1]);
                mma_bf16(acc[1][np * 2],     al1, bh[0], bh[1]);
                mma_bf16(acc[1][np * 2 + 1], ah1, bh[2], bh[3]);
                mma_bf16(acc[1][np * 2 + 1], ah1, bl[2], bl[3]);
                mma_bf16(acc[1][np * 2 + 1], al1, bh[2], bh[3]);
            }
        }

        if (jb + 1 < NJB) {
            CPWAIT0();
            __syncthreads();
        }
    }

    const int mbase = i0 + wy * 32 + (lane >> 2);
    const int dbase = wx * 32 + (lane & 3) * 2;
#pragma unroll
    for (int mi = 0; mi < 2; mi++) {
#pragma unroll
        for (int rr = 0; rr < 2; rr++) {
            const int i = mbase + mi * 16 + rr * 8;
            size_t rowo = (size_t)(r * CC + i) * EE + h * DD;
#pragma unroll
            for (int nf = 0; nf < 4; nf++) {
                store_split2(g_ch, g_cl, rowo + dbase + nf * 8,
                             acc[mi][nf][rr * 2], acc[mi][nf][rr * 2 + 1]);
            }
        }
    }
}

// ---------------------------------------------------------------------------
extern "C" void kernel_launch(void* const* d_in, const int* in_sizes, int n_in,
                              void* d_out, int out_size)
{
    (void)in_sizes; (void)n_in; (void)out_size;
    const float* x  = (const float*)d_in[0];
    const float* wq = (const float*)d_in[1];
    const float* bq = (const float*)d_in[2];
    const float* wk = (const float*)d_in[3];
    const float* bk = (const float*)d_in[4];
    const float* wv = (const float*)d_in[5];
    const float* bv = (const float*)d_in[6];
    const float* wo = (const float*)d_in[7];
    const float* bo = (const float*)d_in[8];
    float* out = (float*)d_out;

    static int smem_configured = 0;
    if (!smem_configured) {
        cudaFuncSetAttribute(qkv_mma_kernel,
                             cudaFuncAttributeMaxDynamicSharedMemorySize, GSMEM);
        cudaFuncSetAttribute(out_mma_kernel,
                             cudaFuncAttributeMaxDynamicSharedMemorySize, GSMEM);
        cudaFuncSetAttribute(logits_mma_kernel,
                             cudaFuncAttributeMaxDynamicSharedMemorySize, GSMEM);
        cudaFuncSetAttribute(context_mma_kernel,
                             cudaFuncAttributeMaxDynamicSharedMemorySize, CSMEM_TOTAL);
        smem_configured = 1;
    }

    pack_x_kernel<<<(MTOK * EE / 4) / 256, 256>>>(x);
    dim3 gw(EE / 32, EE / 32, 4);
    pack_wt_kernel<<<gw, 256>>>(wq, wk, wv, wo);

    dim3 g1(EE / BN, MTOK / BM, 3);               // (6, 256, 3)
    qkv_mma_kernel<<<g1, 256, GSMEM>>>(bq, bk, bv);

    dim3 g2(4, HH, RSPLIT);                       // (4, 12, 16) = 768 CTAs
    logits_mma_kernel<<<g2, 256, GSMEM>>>();

    softmax_kernel<<<HH * CC, 256>>>();

    dim3 g4(CC / BM, RR, HH);                     // (2, 128, 12)
    context_mma_kernel<<<g4, 256, CSMEM_TOTAL>>>();

    dim3 g5(EE / BN, MTOK / BM, 1);               // (6, 256)
    out_mma_kernel<<<g5, 256, GSMEM>>>(bo, out);
}